// round 2
// baseline (speedup 1.0000x reference)
#include <cuda_runtime.h>
#include <math.h>

// Problem constants
#define BB 4
#define NSEQ 2048
#define EMB 2048

// Scratch (no cudaMalloc allowed) — device globals are the sanctioned workaround
__device__ float g_Q[BB * NSEQ * EMB];
__device__ float g_K[BB * NSEQ * EMB];
__device__ float g_V[BB * NSEQ * EMB];
__device__ float g_S[BB * NSEQ * NSEQ];   // scores, overwritten in-place by softmax probs
__device__ float g_O[BB * NSEQ * EMB];

// ---------------------------------------------------------------------------
// Double-buffered tiled SGEMM:
//   C[m,n] = alpha * sum_k A[m,k]*B'[k,n] (+bias[n]) (+maskval*mask[m,n])
//   BT=true : B is [N,K] row-major (NT) — X@W^T, Q@K^T, O@Wo^T
//   BT=false: B is [K,N] row-major (NN) — P@V
// Block tile 128x128, K-tile 16, 256 threads, 8x8 register tile per thread.
// blockIdx.z = batch with element strides sA/sB/sC/sMask.
// ---------------------------------------------------------------------------
template<bool BT, bool HAS_BIAS, bool HAS_MASK>
__global__ void __launch_bounds__(256) sgemm128(
    const float* __restrict__ A, long long sA,
    const float* __restrict__ B, long long sB,
    float* __restrict__ C, long long sC,
    const float* __restrict__ bias,
    const int* __restrict__ mask, long long sMask,
    int M, int N, int K, float alpha, float maskval)
{
    __shared__ float As[2][16][128];
    __shared__ float Bs[2][16][128];

    const int bz = blockIdx.z;
    A += (long long)bz * sA;
    B += (long long)bz * sB;
    C += (long long)bz * sC;
    if (HAS_MASK) mask += (long long)bz * sMask;

    const int tid = threadIdx.x;
    const int m0 = blockIdx.y * 128;
    const int n0 = blockIdx.x * 128;
    const int tx = tid & 15;   // n sub-tile
    const int ty = tid >> 4;   // m sub-tile

    // per-thread load coordinates (2 float4 each for A and B)
    int a_row[2], a_kq[2];
    int b_i0[2], b_i1[2];      // BT: (row, kq)   NN: (kk, nq)
    #pragma unroll
    for (int it = 0; it < 2; it++) {
        int idx = tid + it * 256;          // 0..511
        a_row[it] = idx >> 2;              // 0..127
        a_kq[it]  = (idx & 3) << 2;        // 0,4,8,12
        if (BT) { b_i0[it] = idx >> 2; b_i1[it] = (idx & 3) << 2; }
        else    { b_i0[it] = idx >> 5; b_i1[it] = (idx & 31) << 2; }
    }

    float acc[8][8];
    #pragma unroll
    for (int i = 0; i < 8; i++)
        #pragma unroll
        for (int j = 0; j < 8; j++) acc[i][j] = 0.f;

    // ---- prologue: load tile 0 into buffer 0 ----
    {
        #pragma unroll
        for (int it = 0; it < 2; it++) {
            float4 v = *reinterpret_cast<const float4*>(
                &A[(long long)(m0 + a_row[it]) * K + a_kq[it]]);
            As[0][a_kq[it] + 0][a_row[it]] = v.x;
            As[0][a_kq[it] + 1][a_row[it]] = v.y;
            As[0][a_kq[it] + 2][a_row[it]] = v.z;
            As[0][a_kq[it] + 3][a_row[it]] = v.w;
            if (BT) {
                float4 w = *reinterpret_cast<const float4*>(
                    &B[(long long)(n0 + b_i0[it]) * K + b_i1[it]]);
                Bs[0][b_i1[it] + 0][b_i0[it]] = w.x;
                Bs[0][b_i1[it] + 1][b_i0[it]] = w.y;
                Bs[0][b_i1[it] + 2][b_i0[it]] = w.z;
                Bs[0][b_i1[it] + 3][b_i0[it]] = w.w;
            } else {
                float4 w = *reinterpret_cast<const float4*>(
                    &B[(long long)b_i0[it] * N + n0 + b_i1[it]]);
                *reinterpret_cast<float4*>(&Bs[0][b_i0[it]][b_i1[it]]) = w;
            }
        }
    }
    __syncthreads();

    const int numTiles = K >> 4;
    int buf = 0;
    for (int t = 0; t < numTiles; t++) {
        // ---- prefetch next tile into registers ----
        float4 pa[2], pb[2];
        const bool more = (t + 1 < numTiles);
        if (more) {
            int k0 = (t + 1) << 4;
            #pragma unroll
            for (int it = 0; it < 2; it++) {
                pa[it] = *reinterpret_cast<const float4*>(
                    &A[(long long)(m0 + a_row[it]) * K + k0 + a_kq[it]]);
                if (BT)
                    pb[it] = *reinterpret_cast<const float4*>(
                        &B[(long long)(n0 + b_i0[it]) * K + k0 + b_i1[it]]);
                else
                    pb[it] = *reinterpret_cast<const float4*>(
                        &B[(long long)(k0 + b_i0[it]) * N + n0 + b_i1[it]]);
            }
        }

        // ---- compute current tile ----
        #pragma unroll
        for (int kk = 0; kk < 16; kk++) {
            float ar[8], br[8];
            float4 a0 = *reinterpret_cast<const float4*>(&As[buf][kk][ty * 8 + 0]);
            float4 a1 = *reinterpret_cast<const float4*>(&As[buf][kk][ty * 8 + 4]);
            float4 b0 = *reinterpret_cast<const float4*>(&Bs[buf][kk][tx * 8 + 0]);
            float4 b1 = *reinterpret_cast<const float4*>(&Bs[buf][kk][tx * 8 + 4]);
            ar[0]=a0.x; ar[1]=a0.y; ar[2]=a0.z; ar[3]=a0.w;
            ar[4]=a1.x; ar[5]=a1.y; ar[6]=a1.z; ar[7]=a1.w;
            br[0]=b0.x; br[1]=b0.y; br[2]=b0.z; br[3]=b0.w;
            br[4]=b1.x; br[5]=b1.y; br[6]=b1.z; br[7]=b1.w;
            #pragma unroll
            for (int i = 0; i < 8; i++)
                #pragma unroll
                for (int j = 0; j < 8; j++)
                    acc[i][j] += ar[i] * br[j];
        }

        // ---- store prefetched tile into other buffer ----
        if (more) {
            int nb = buf ^ 1;
            #pragma unroll
            for (int it = 0; it < 2; it++) {
                As[nb][a_kq[it] + 0][a_row[it]] = pa[it].x;
                As[nb][a_kq[it] + 1][a_row[it]] = pa[it].y;
                As[nb][a_kq[it] + 2][a_row[it]] = pa[it].z;
                As[nb][a_kq[it] + 3][a_row[it]] = pa[it].w;
                if (BT) {
                    Bs[nb][b_i1[it] + 0][b_i0[it]] = pb[it].x;
                    Bs[nb][b_i1[it] + 1][b_i0[it]] = pb[it].y;
                    Bs[nb][b_i1[it] + 2][b_i0[it]] = pb[it].z;
                    Bs[nb][b_i1[it] + 3][b_i0[it]] = pb[it].w;
                } else {
                    *reinterpret_cast<float4*>(&Bs[nb][b_i0[it]][b_i1[it]]) = pb[it];
                }
            }
            __syncthreads();
            buf = nb;
        }
    }

    // ---- epilogue: alpha, bias, mask, vectorized stores ----
    #pragma unroll
    for (int i = 0; i < 8; i++) {
        long long m = m0 + ty * 8 + i;
        #pragma unroll
        for (int jj = 0; jj < 2; jj++) {
            int n = n0 + tx * 8 + jj * 4;
            float4 c;
            c.x = acc[i][jj * 4 + 0] * alpha;
            c.y = acc[i][jj * 4 + 1] * alpha;
            c.z = acc[i][jj * 4 + 2] * alpha;
            c.w = acc[i][jj * 4 + 3] * alpha;
            if (HAS_BIAS) {
                float4 bv = *reinterpret_cast<const float4*>(&bias[n]);
                c.x += bv.x; c.y += bv.y; c.z += bv.z; c.w += bv.w;
            }
            if (HAS_MASK) {
                int4 mv = *reinterpret_cast<const int4*>(&mask[m * N + n]);
                c.x += maskval * (float)mv.x;
                c.y += maskval * (float)mv.y;
                c.z += maskval * (float)mv.z;
                c.w += maskval * (float)mv.w;
            }
            *reinterpret_cast<float4*>(&C[m * N + n]) = c;
        }
    }
}

// ---------------------------------------------------------------------------
// Fused edge gate + row softmax, in place on S. One 256-thread block per row.
//   g   = sigmoid(S[row,:] . We + be)        (sigmoid saturates to exact 0/1
//                                             for the ±1e9-dominated dots)
//   S[row,:] = softmax(g * S[row,:])
// ---------------------------------------------------------------------------
__global__ void __launch_bounds__(256) softmax_gate_kernel(
    float* __restrict__ S, const float* __restrict__ We,
    const float* __restrict__ be)
{
    const int row = blockIdx.x;
    float* s = S + (long long)row * NSEQ;
    const int t = threadIdx.x;
    __shared__ float red[256];

    // load row + gate dot
    float x[NSEQ / 256];
    float part = 0.f;
    #pragma unroll
    for (int i = 0; i < NSEQ / 256; i++) {
        int idx = t + i * 256;
        x[i] = s[idx];
        part += x[i] * We[idx];
    }
    red[t] = part;
    __syncthreads();
    #pragma unroll
    for (int off = 128; off > 0; off >>= 1) {
        if (t < off) red[t] += red[t + off];
        __syncthreads();
    }
    const float gv = 1.f / (1.f + expf(-(red[0] + be[0])));
    __syncthreads();

    // max
    float mx = -INFINITY;
    #pragma unroll
    for (int i = 0; i < NSEQ / 256; i++) {
        x[i] *= gv;
        mx = fmaxf(mx, x[i]);
    }
    red[t] = mx;
    __syncthreads();
    #pragma unroll
    for (int off = 128; off > 0; off >>= 1) {
        if (t < off) red[t] = fmaxf(red[t], red[t + off]);
        __syncthreads();
    }
    mx = red[0];
    __syncthreads();

    // exp + sum
    float sum = 0.f;
    #pragma unroll
    for (int i = 0; i < NSEQ / 256; i++) {
        x[i] = expf(x[i] - mx);
        sum += x[i];
    }
    red[t] = sum;
    __syncthreads();
    #pragma unroll
    for (int off = 128; off > 0; off >>= 1) {
        if (t < off) red[t] += red[t + off];
        __syncthreads();
    }
    const float inv = 1.f / red[0];
    #pragma unroll
    for (int i = 0; i < NSEQ / 256; i++)
        s[t + i * 256] = x[i] * inv;
}

// ---------------------------------------------------------------------------
// Launch
// ---------------------------------------------------------------------------
extern "C" void kernel_launch(void* const* d_in, const int* in_sizes, int n_in,
                              void* d_out, int out_size)
{
    (void)in_sizes; (void)n_in; (void)out_size;
    const float* query = (const float*)d_in[0];
    const float* key_  = (const float*)d_in[1];
    const float* value = (const float*)d_in[2];
    const int*   mask  = (const int*)d_in[3];
    const float* Wq = (const float*)d_in[4];
    const float* bq = (const float*)d_in[5];
    const float* Wk = (const float*)d_in[6];
    const float* bk = (const float*)d_in[7];
    const float* Wv = (const float*)d_in[8];
    const float* bv = (const float*)d_in[9];
    const float* We = (const float*)d_in[10];
    const float* be = (const float*)d_in[11];
    const float* Wo = (const float*)d_in[12];
    const float* bo = (const float*)d_in[13];
    float* out = (float*)d_out;

    float *Qd, *Kd, *Vd, *Sd, *Od;
    cudaGetSymbolAddress((void**)&Qd, g_Q);
    cudaGetSymbolAddress((void**)&Kd, g_K);
    cudaGetSymbolAddress((void**)&Vd, g_V);
    cudaGetSymbolAddress((void**)&Sd, g_S);
    cudaGetSymbolAddress((void**)&Od, g_O);

    const long long NE = (long long)NSEQ * EMB;   // per-batch element stride
    const long long NN = (long long)NSEQ * NSEQ;
    const int Mflat = BB * NSEQ;                  // 8192
    const float scale = 1.f / sqrtf((float)EMB);

    dim3 gridProj(EMB / 128, Mflat / 128, 1);     // (16, 64)
    dim3 gridBat(NSEQ / 128, NSEQ / 128, BB);     // (16, 16, 4)

    // Q/K/V projections: X @ W^T + b   (NT, bias)
    sgemm128<true, true, false><<<gridProj, 256>>>(
        query, 0, Wq, 0, Qd, 0, bq, nullptr, 0, Mflat, EMB, EMB, 1.f, 0.f);
    sgemm128<true, true, false><<<gridProj, 256>>>(
        key_, 0, Wk, 0, Kd, 0, bk, nullptr, 0, Mflat, EMB, EMB, 1.f, 0.f);
    sgemm128<true, true, false><<<gridProj, 256>>>(
        value, 0, Wv, 0, Vd, 0, bv, nullptr, 0, Mflat, EMB, EMB, 1.f, 0.f);

    // scores = scale * Q @ K^T + (-1e9) * mask   (NT, mask epilogue, batched)
    sgemm128<true, false, true><<<gridBat, 256>>>(
        Qd, NE, Kd, NE, Sd, NN, nullptr, mask, NN,
        NSEQ, NSEQ, EMB, scale, -1e9f);

    // fused edge gate + row softmax (in place on S)
    softmax_gate_kernel<<<BB * NSEQ, 256>>>(Sd, We, be);

    // O = P @ V   (NN, batched)
    sgemm128<false, false, false><<<gridBat, 256>>>(
        Sd, NN, Vd, NE, Od, NE, nullptr, nullptr, 0,
        NSEQ, EMB, NSEQ, 1.f, 0.f);

    // out = O @ Wo^T + bo   (NT, bias)
    sgemm128<true, true, false><<<gridProj, 256>>>(
        Od, 0, Wo, 0, out, 0, bo, nullptr, 0, Mflat, EMB, EMB, 1.f, 0.f);
}

// round 5
// speedup vs baseline: 2.6953x; 2.6953x over previous
#include <cuda_runtime.h>
#include <cuda_bf16.h>
#include <stdint.h>
#include <math.h>

// Problem constants
#define BB 4
#define NSEQ 2048
#define EMB 2048

// Scratch (no cudaMalloc allowed)
__device__ float g_Q[BB * NSEQ * EMB];
__device__ float g_K[BB * NSEQ * EMB];
__device__ float g_V[BB * NSEQ * EMB];
__device__ float g_S[BB * NSEQ * NSEQ];   // scores -> probs in place
__device__ float g_O[BB * NSEQ * EMB];

// ---------------------------------------------------------------------------
// fp32 -> bf16 hi/lo split of a float4, packed as uint2 (4 bf16 each)
// ---------------------------------------------------------------------------
__device__ __forceinline__ void split4(const float4 v, uint2& hi, uint2& lo)
{
    __nv_bfloat16 h0 = __float2bfloat16_rn(v.x);
    __nv_bfloat16 h1 = __float2bfloat16_rn(v.y);
    __nv_bfloat16 h2 = __float2bfloat16_rn(v.z);
    __nv_bfloat16 h3 = __float2bfloat16_rn(v.w);
    __nv_bfloat16 l0 = __float2bfloat16_rn(v.x - __bfloat162float(h0));
    __nv_bfloat16 l1 = __float2bfloat16_rn(v.y - __bfloat162float(h1));
    __nv_bfloat16 l2 = __float2bfloat16_rn(v.z - __bfloat162float(h2));
    __nv_bfloat16 l3 = __float2bfloat16_rn(v.w - __bfloat162float(h3));
    hi.x = (unsigned)__bfloat16_as_ushort(h0) | ((unsigned)__bfloat16_as_ushort(h1) << 16);
    hi.y = (unsigned)__bfloat16_as_ushort(h2) | ((unsigned)__bfloat16_as_ushort(h3) << 16);
    lo.x = (unsigned)__bfloat16_as_ushort(l0) | ((unsigned)__bfloat16_as_ushort(l1) << 16);
    lo.y = (unsigned)__bfloat16_as_ushort(l2) | ((unsigned)__bfloat16_as_ushort(l3) << 16);
}

#define LDSM4(R0, R1, R2, R3, ADDR)                                         \
    asm volatile("ldmatrix.sync.aligned.m8n8.x4.shared.b16 {%0,%1,%2,%3}, [%4];" \
                 : "=r"(R0), "=r"(R1), "=r"(R2), "=r"(R3) : "r"(ADDR))

#define LDSM4T(R0, R1, R2, R3, ADDR)                                        \
    asm volatile("ldmatrix.sync.aligned.m8n8.x4.trans.shared.b16 {%0,%1,%2,%3}, [%4];" \
                 : "=r"(R0), "=r"(R1), "=r"(R2), "=r"(R3) : "r"(ADDR))

#define MMA16816(D, A0, A1, A2, A3, B0, B1)                                 \
    asm volatile("mma.sync.aligned.m16n8k16.row.col.f32.bf16.bf16.f32 "     \
                 "{%0,%1,%2,%3},{%4,%5,%6,%7},{%8,%9},{%0,%1,%2,%3};"       \
                 : "+f"((D)[0]), "+f"((D)[1]), "+f"((D)[2]), "+f"((D)[3])   \
                 : "r"(A0), "r"(A1), "r"(A2), "r"(A3), "r"(B0), "r"(B1))

// ---------------------------------------------------------------------------
// Tensor-core GEMM with bf16 hi/lo split (3-term, ~fp32 accuracy):
//   C = alpha * A @ B' (+bias[n]) (+maskval*mask[m,n])
//   BT=true : B is [N,K] row-major (NT) — X@W^T, Q@K^T, O@Wo^T
//   BT=false: B is [K,N] row-major (NN) — P@V
// Block tile 128x128, K-tile 16, 256 threads (8 warps, 32x64 warp tiles),
// mma.sync.m16n8k16 bf16, double-buffered SMEM, padded pitches for ldmatrix.
// ---------------------------------------------------------------------------
template<bool BT, bool HAS_BIAS, bool HAS_MASK>
__global__ void __launch_bounds__(256) hgemm128(
    const float* __restrict__ A, long long sA,
    const float* __restrict__ B, long long sB,
    float* __restrict__ C, long long sC,
    const float* __restrict__ bias,
    const int* __restrict__ mask, long long sMask,
    int M, int N, int K, float alpha, float maskval)
{
    // A: 128 rows x 16 k, pitch 24 (bank-conflict-free ldmatrix)
    // B (BT): 128 n-rows x 16 k, pitch 24 ; B (NN): 16 k-rows x 128 n, pitch 136
    __shared__ __align__(16) unsigned short Ah[2][3072], Al[2][3072];
    __shared__ __align__(16) unsigned short Bh[2][3072], Bl[2][3072];

    const int bz = blockIdx.z;
    A += (long long)bz * sA;
    B += (long long)bz * sB;
    C += (long long)bz * sC;
    if (HAS_MASK) mask += (long long)bz * sMask;

    const int tid  = threadIdx.x;
    const int lane = tid & 31;
    const int warp = tid >> 5;
    const int wm = (warp >> 1) * 32;   // warp m origin within block tile
    const int wn = (warp & 1) * 64;    // warp n origin
    const int m0 = blockIdx.y * 128;
    const int n0 = blockIdx.x * 128;

    // global-load coordinates (2 float4 per thread for each of A and B)
    int a_row[2], a_kq[2], b_i0[2], b_i1[2];
    #pragma unroll
    for (int it = 0; it < 2; it++) {
        int idx = tid + it * 256;              // 0..511
        a_row[it] = idx >> 2;                  // 0..127
        a_kq[it]  = (idx & 3) << 2;            // 0,4,8,12
        if (BT) { b_i0[it] = idx >> 2; b_i1[it] = (idx & 3) << 2; }   // (n, k)
        else    { b_i0[it] = idx >> 5; b_i1[it] = (idx & 31) << 2; }  // (k, n)
    }

    float acc[2][8][4];
    #pragma unroll
    for (int i = 0; i < 2; i++)
        #pragma unroll
        for (int j = 0; j < 8; j++)
            #pragma unroll
            for (int c = 0; c < 4; c++) acc[i][j][c] = 0.f;

    // ---- prologue: tile 0 -> buffer 0 ----
    #pragma unroll
    for (int it = 0; it < 2; it++) {
        float4 va = *reinterpret_cast<const float4*>(
            &A[(long long)(m0 + a_row[it]) * K + a_kq[it]]);
        uint2 h, l; split4(va, h, l);
        *reinterpret_cast<uint2*>(&Ah[0][a_row[it] * 24 + a_kq[it]]) = h;
        *reinterpret_cast<uint2*>(&Al[0][a_row[it] * 24 + a_kq[it]]) = l;
        float4 vb;
        int soff;
        if (BT) {
            vb = *reinterpret_cast<const float4*>(
                &B[(long long)(n0 + b_i0[it]) * K + b_i1[it]]);
            soff = b_i0[it] * 24 + b_i1[it];
        } else {
            vb = *reinterpret_cast<const float4*>(
                &B[(long long)b_i0[it] * N + n0 + b_i1[it]]);
            soff = b_i0[it] * 136 + b_i1[it];
        }
        split4(vb, h, l);
        *reinterpret_cast<uint2*>(&Bh[0][soff]) = h;
        *reinterpret_cast<uint2*>(&Bl[0][soff]) = l;
    }
    __syncthreads();

    // ldmatrix source offsets (bytes, within a buffer)
    const uint32_t a_off = (uint32_t)(((wm + (lane & 15)) * 24 + ((lane >> 4) << 3)) * 2);
    uint32_t b_off;
    if (BT) b_off = (uint32_t)(((wn + (lane & 7) + ((lane >> 4) << 3)) * 24 +
                                (((lane >> 3) & 1) << 3)) * 2);
    else    b_off = (uint32_t)(((lane & 15) * 136 + wn + ((lane >> 4) << 3)) * 2);

    const int numTiles = K >> 4;
    int buf = 0;
    for (int t = 0; t < numTiles; t++) {
        // ---- prefetch next tile (fp32) into registers ----
        float4 pa[2], pb[2];
        const bool more = (t + 1 < numTiles);
        if (more) {
            int k0 = (t + 1) << 4;
            #pragma unroll
            for (int it = 0; it < 2; it++) {
                pa[it] = *reinterpret_cast<const float4*>(
                    &A[(long long)(m0 + a_row[it]) * K + k0 + a_kq[it]]);
                if (BT)
                    pb[it] = *reinterpret_cast<const float4*>(
                        &B[(long long)(n0 + b_i0[it]) * K + k0 + b_i1[it]]);
                else
                    pb[it] = *reinterpret_cast<const float4*>(
                        &B[(long long)(k0 + b_i0[it]) * N + n0 + b_i1[it]]);
            }
        }

        // ---- compute on current buffer ----
        const uint32_t ah_b = (uint32_t)__cvta_generic_to_shared(&Ah[buf][0]);
        const uint32_t al_b = (uint32_t)__cvta_generic_to_shared(&Al[buf][0]);
        const uint32_t bh_b = (uint32_t)__cvta_generic_to_shared(&Bh[buf][0]);
        const uint32_t bl_b = (uint32_t)__cvta_generic_to_shared(&Bl[buf][0]);

        unsigned ahf[2][4], alf[2][4];
        #pragma unroll
        for (int mi = 0; mi < 2; mi++) {
            LDSM4(ahf[mi][0], ahf[mi][1], ahf[mi][2], ahf[mi][3],
                  ah_b + a_off + mi * 768);
            LDSM4(alf[mi][0], alf[mi][1], alf[mi][2], alf[mi][3],
                  al_b + a_off + mi * 768);
        }

        #pragma unroll
        for (int g = 0; g < 4; g++) {
            unsigned bhf[4], blf[4];
            const uint32_t off = b_off + (BT ? (uint32_t)(g * 768) : (uint32_t)(g * 32));
            if (BT) {
                LDSM4 (bhf[0], bhf[1], bhf[2], bhf[3], bh_b + off);
                LDSM4 (blf[0], blf[1], blf[2], blf[3], bl_b + off);
            } else {
                LDSM4T(bhf[0], bhf[1], bhf[2], bhf[3], bh_b + off);
                LDSM4T(blf[0], blf[1], blf[2], blf[3], bl_b + off);
            }
            #pragma unroll
            for (int mi = 0; mi < 2; mi++) {
                MMA16816(acc[mi][2 * g],     ahf[mi][0], ahf[mi][1], ahf[mi][2], ahf[mi][3], bhf[0], bhf[1]);
                MMA16816(acc[mi][2 * g],     alf[mi][0], alf[mi][1], alf[mi][2], alf[mi][3], bhf[0], bhf[1]);
                MMA16816(acc[mi][2 * g],     ahf[mi][0], ahf[mi][1], ahf[mi][2], ahf[mi][3], blf[0], blf[1]);
                MMA16816(acc[mi][2 * g + 1], ahf[mi][0], ahf[mi][1], ahf[mi][2], ahf[mi][3], bhf[2], bhf[3]);
                MMA16816(acc[mi][2 * g + 1], alf[mi][0], alf[mi][1], alf[mi][2], alf[mi][3], bhf[2], bhf[3]);
                MMA16816(acc[mi][2 * g + 1], ahf[mi][0], ahf[mi][1], ahf[mi][2], ahf[mi][3], blf[2], blf[3]);
            }
        }

        // ---- store prefetched tile into other buffer ----
        if (more) {
            int nb = buf ^ 1;
            #pragma unroll
            for (int it = 0; it < 2; it++) {
                uint2 h, l; split4(pa[it], h, l);
                *reinterpret_cast<uint2*>(&Ah[nb][a_row[it] * 24 + a_kq[it]]) = h;
                *reinterpret_cast<uint2*>(&Al[nb][a_row[it] * 24 + a_kq[it]]) = l;
                int soff = BT ? (b_i0[it] * 24 + b_i1[it]) : (b_i0[it] * 136 + b_i1[it]);
                split4(pb[it], h, l);
                *reinterpret_cast<uint2*>(&Bh[nb][soff]) = h;
                *reinterpret_cast<uint2*>(&Bl[nb][soff]) = l;
            }
            __syncthreads();
            buf = nb;
        }
    }

    // ---- epilogue: alpha, bias, mask, float2 stores ----
    #pragma unroll
    for (int mi = 0; mi < 2; mi++) {
        #pragma unroll
        for (int nf = 0; nf < 8; nf++) {
            const int col = n0 + wn + nf * 8 + (lane & 3) * 2;
            const long long r0 = m0 + wm + mi * 16 + (lane >> 2);
            const long long r1 = r0 + 8;
            float2 p0, p1;
            p0.x = acc[mi][nf][0] * alpha; p0.y = acc[mi][nf][1] * alpha;
            p1.x = acc[mi][nf][2] * alpha; p1.y = acc[mi][nf][3] * alpha;
            if (HAS_BIAS) {
                float b0 = bias[col], b1 = bias[col + 1];
                p0.x += b0; p0.y += b1; p1.x += b0; p1.y += b1;
            }
            if (HAS_MASK) {
                int2 mv0 = *reinterpret_cast<const int2*>(&mask[r0 * N + col]);
                int2 mv1 = *reinterpret_cast<const int2*>(&mask[r1 * N + col]);
                p0.x += maskval * (float)mv0.x; p0.y += maskval * (float)mv0.y;
                p1.x += maskval * (float)mv1.x; p1.y += maskval * (float)mv1.y;
            }
            *reinterpret_cast<float2*>(&C[r0 * N + col]) = p0;
            *reinterpret_cast<float2*>(&C[r1 * N + col]) = p1;
        }
    }
}

// ---------------------------------------------------------------------------
// Fused edge gate + row softmax, in place on S. One 256-thread block per row.
// ---------------------------------------------------------------------------
__global__ void __launch_bounds__(256) softmax_gate_kernel(
    float* __restrict__ S, const float* __restrict__ We,
    const float* __restrict__ be)
{
    const int row = blockIdx.x;
    float* s = S + (long long)row * NSEQ;
    const int t = threadIdx.x;
    __shared__ float red[256];

    float x[NSEQ / 256];
    float part = 0.f;
    #pragma unroll
    for (int i = 0; i < NSEQ / 256; i++) {
        int idx = t + i * 256;
        x[i] = s[idx];
        part += x[i] * We[idx];
    }
    red[t] = part;
    __syncthreads();
    #pragma unroll
    for (int off = 128; off > 0; off >>= 1) {
        if (t < off) red[t] += red[t + off];
        __syncthreads();
    }
    const float gv = 1.f / (1.f + expf(-(red[0] + be[0])));
    __syncthreads();

    float mx = -INFINITY;
    #pragma unroll
    for (int i = 0; i < NSEQ / 256; i++) {
        x[i] *= gv;
        mx = fmaxf(mx, x[i]);
    }
    red[t] = mx;
    __syncthreads();
    #pragma unroll
    for (int off = 128; off > 0; off >>= 1) {
        if (t < off) red[t] = fmaxf(red[t], red[t + off]);
        __syncthreads();
    }
    mx = red[0];
    __syncthreads();

    float sum = 0.f;
    #pragma unroll
    for (int i = 0; i < NSEQ / 256; i++) {
        x[i] = expf(x[i] - mx);
        sum += x[i];
    }
    red[t] = sum;
    __syncthreads();
    #pragma unroll
    for (int off = 128; off > 0; off >>= 1) {
        if (t < off) red[t] += red[t + off];
        __syncthreads();
    }
    const float inv = 1.f / red[0];
    #pragma unroll
    for (int i = 0; i < NSEQ / 256; i++)
        s[t + i * 256] = x[i] * inv;
}

// ---------------------------------------------------------------------------
// Launch
// ---------------------------------------------------------------------------
extern "C" void kernel_launch(void* const* d_in, const int* in_sizes, int n_in,
                              void* d_out, int out_size)
{
    (void)in_sizes; (void)n_in; (void)out_size;
    const float* query = (const float*)d_in[0];
    const float* key_  = (const float*)d_in[1];
    const float* value = (const float*)d_in[2];
    const int*   mask  = (const int*)d_in[3];
    const float* Wq = (const float*)d_in[4];
    const float* bq = (const float*)d_in[5];
    const float* Wk = (const float*)d_in[6];
    const float* bk = (const float*)d_in[7];
    const float* Wv = (const float*)d_in[8];
    const float* bv = (const float*)d_in[9];
    const float* We = (const float*)d_in[10];
    const float* be = (const float*)d_in[11];
    const float* Wo = (const float*)d_in[12];
    const float* bo = (const float*)d_in[13];
    float* out = (float*)d_out;

    float *Qd, *Kd, *Vd, *Sd, *Od;
    cudaGetSymbolAddress((void**)&Qd, g_Q);
    cudaGetSymbolAddress((void**)&Kd, g_K);
    cudaGetSymbolAddress((void**)&Vd, g_V);
    cudaGetSymbolAddress((void**)&Sd, g_S);
    cudaGetSymbolAddress((void**)&Od, g_O);

    const long long NE = (long long)NSEQ * EMB;
    const long long NN = (long long)NSEQ * NSEQ;
    const int Mflat = BB * NSEQ;                  // 8192
    const float scale = 1.f / sqrtf((float)EMB);

    dim3 gridProj(EMB / 128, Mflat / 128, 1);     // (16, 64)
    dim3 gridBat(NSEQ / 128, NSEQ / 128, BB);     // (16, 16, 4)

    // Q/K/V projections: X @ W^T + b   (NT, bias)
    hgemm128<true, true, false><<<gridProj, 256>>>(
        query, 0, Wq, 0, Qd, 0, bq, nullptr, 0, Mflat, EMB, EMB, 1.f, 0.f);
    hgemm128<true, true, false><<<gridProj, 256>>>(
        key_, 0, Wk, 0, Kd, 0, bk, nullptr, 0, Mflat, EMB, EMB, 1.f, 0.f);
    hgemm128<true, true, false><<<gridProj, 256>>>(
        value, 0, Wv, 0, Vd, 0, bv, nullptr, 0, Mflat, EMB, EMB, 1.f, 0.f);

    // scores = scale * Q @ K^T + (-1e9) * mask   (NT, mask epilogue, batched)
    hgemm128<true, false, true><<<gridBat, 256>>>(
        Qd, NE, Kd, NE, Sd, NN, nullptr, mask, NN,
        NSEQ, NSEQ, EMB, scale, -1e9f);

    // fused edge gate + row softmax (in place on S)
    softmax_gate_kernel<<<BB * NSEQ, 256>>>(Sd, We, be);

    // O = P @ V   (NN, batched)
    hgemm128<false, false, false><<<gridBat, 256>>>(
        Sd, NN, Vd, NE, Od, NE, nullptr, nullptr, 0,
        NSEQ, EMB, NSEQ, 1.f, 0.f);

    // out = O @ Wo^T + bo   (NT, bias)
    hgemm128<true, true, false><<<gridProj, 256>>>(
        Od, 0, Wo, 0, out, 0, bo, nullptr, 0, Mflat, EMB, EMB, 1.f, 0.f);
}